// round 6
// baseline (speedup 1.0000x reference)
#include <cuda_runtime.h>
#include <cstdint>

constexpr int B_ = 8;     // batch
constexpr int Q_ = 128;   // queries
constexpr int K_ = 1024;  // keys
constexpr int D_ = 512;   // qk feature dim
constexpr int H_ = 256;   // hidden
constexpr int V_ = 512;   // value dim
constexpr int MK = B_ * K_;   // 8192 rows of kproj

// Scratch (no cudaMalloc allowed)
__device__ float g_qproj [B_ * Q_ * H_];   // [B*Q][H]   1 MB
__device__ float g_kprojT[H_ * B_ * K_];   // [H][B*K]   8 MB (transposed)
__device__ float g_scores[B_ * Q_ * K_];   // [B*Q][K]   4 MB

__device__ __forceinline__ float tanh_fast(float x) {
    float y;
    asm("tanh.approx.f32 %0, %1;" : "=f"(y) : "f"(x));
    return y;
}
__device__ __forceinline__ unsigned long long pack2(float lo, float hi) {
    unsigned long long r;
    asm("mov.b64 %0, {%1, %2};" : "=l"(r) : "f"(lo), "f"(hi));
    return r;
}
__device__ __forceinline__ float2 unpack2(unsigned long long v) {
    float2 r;
    asm("mov.b64 {%0, %1}, %2;" : "=f"(r.x), "=f"(r.y) : "l"(v));
    return r;
}
__device__ __forceinline__ unsigned long long fma2(unsigned long long a,
                                                   unsigned long long b,
                                                   unsigned long long c) {
    unsigned long long d;
    asm("fma.rn.f32x2 %0, %1, %2, %3;" : "=l"(d) : "l"(a), "l"(b), "l"(c));
    return d;
}
__device__ __forceinline__ unsigned long long add2(unsigned long long a,
                                                   unsigned long long b) {
    unsigned long long d;
    asm("add.rn.f32x2 %0, %1, %2;" : "=l"(d) : "l"(a), "l"(b));
    return d;
}

// ----------------------------------------------------------------------------
// K1: merged projection GEMM v3.
// 128x64 tile, BK=16, 128 threads, 8x8 microtile (1.0 B LDS / FMA),
// double-buffered smem, masked early-exit on kproj tiles.
//   blockIdx.y <  8 : qproj row tile -> g_qproj  [B*Q][H]
//   blockIdx.y >= 8 : kproj row tile -> g_kprojT [H][B*K] (transposed)
// ----------------------------------------------------------------------------
__global__ __launch_bounds__(128)
void proj_gemm(const float* __restrict__ queries, const float* __restrict__ keys,
               const float* __restrict__ Wq, const float* __restrict__ Wk,
               const int* __restrict__ vlens)
{
    constexpr int BM = 128, BN = 64, BK = 16;
    __shared__ float As[2][BK][BM + 4];
    __shared__ float Bs[2][BK][BN];

    const int tid = threadIdx.x;
    const bool isQ = (blockIdx.y < 8);
    const float* A;
    const float* W;
    long long row0;
    if (isQ) {
        A = queries; W = Wq; row0 = (long long)blockIdx.y * BM;
    } else {
        int r  = (int)(blockIdx.y - 8) * BM;
        int b  = r >> 10;
        int k0 = r & 1023;
        if (k0 >= vlens[b]) return;     // masked kproj tile
        A = keys; W = Wk; row0 = r;
    }
    const int col0 = blockIdx.x * BN;

    const int ty = tid >> 3, tx = tid & 7;
    const int r0 = ty * 8, c0 = tx * 8;

    // loader mappings
    int arow[4], ac4[4];
    #pragma unroll
    for (int u = 0; u < 4; u++) {
        int l = tid * 4 + u;
        arow[u] = l >> 2;  ac4[u] = (l & 3) << 2;   // 128 rows x 16 cols
    }
    int brow[2], bc4[2];
    #pragma unroll
    for (int u = 0; u < 2; u++) {
        int l = tid * 2 + u;
        brow[u] = l >> 4;  bc4[u] = (l & 15) << 2;  // 16 rows x 64 cols
    }

    unsigned long long acc[8][4];
    #pragma unroll
    for (int i = 0; i < 8; i++)
        #pragma unroll
        for (int j = 0; j < 4; j++) acc[i][j] = 0ull;

    float4 avr[4], bvr[2];
    #pragma unroll
    for (int u = 0; u < 4; u++)
        avr[u] = *(const float4*)(A + (row0 + arow[u]) * D_ + ac4[u]);
    #pragma unroll
    for (int u = 0; u < 2; u++)
        bvr[u] = *(const float4*)(W + (long long)brow[u] * H_ + col0 + bc4[u]);
    #pragma unroll
    for (int u = 0; u < 4; u++) {
        As[0][ac4[u] + 0][arow[u]] = avr[u].x;
        As[0][ac4[u] + 1][arow[u]] = avr[u].y;
        As[0][ac4[u] + 2][arow[u]] = avr[u].z;
        As[0][ac4[u] + 3][arow[u]] = avr[u].w;
    }
    #pragma unroll
    for (int u = 0; u < 2; u++)
        *(float4*)&Bs[0][brow[u]][bc4[u]] = bvr[u];
    __syncthreads();

    constexpr int NKB = D_ / BK;   // 32
    for (int it = 0; it < NKB; it++) {
        const int cur = it & 1;
        if (it + 1 < NKB) {
            const int kb = (it + 1) * BK;
            #pragma unroll
            for (int u = 0; u < 4; u++)
                avr[u] = *(const float4*)(A + (row0 + arow[u]) * D_ + kb + ac4[u]);
            #pragma unroll
            for (int u = 0; u < 2; u++)
                bvr[u] = *(const float4*)(W + (long long)(kb + brow[u]) * H_ + col0 + bc4[u]);
        }
        #pragma unroll
        for (int kk = 0; kk < BK; kk++) {
            float4 a0 = *(const float4*)&As[cur][kk][r0];
            float4 a1 = *(const float4*)&As[cur][kk][r0 + 4];
            float4 b0 = *(const float4*)&Bs[cur][kk][c0];
            float4 b1 = *(const float4*)&Bs[cur][kk][c0 + 4];
            unsigned long long bp[4] = {pack2(b0.x, b0.y), pack2(b0.z, b0.w),
                                        pack2(b1.x, b1.y), pack2(b1.z, b1.w)};
            float a[8] = {a0.x, a0.y, a0.z, a0.w, a1.x, a1.y, a1.z, a1.w};
            #pragma unroll
            for (int ii = 0; ii < 8; ii++) {
                unsigned long long a2 = pack2(a[ii], a[ii]);
                #pragma unroll
                for (int jj = 0; jj < 4; jj++)
                    acc[ii][jj] = fma2(a2, bp[jj], acc[ii][jj]);
            }
        }
        if (it + 1 < NKB) {
            const int nxt = 1 - cur;
            #pragma unroll
            for (int u = 0; u < 4; u++) {
                As[nxt][ac4[u] + 0][arow[u]] = avr[u].x;
                As[nxt][ac4[u] + 1][arow[u]] = avr[u].y;
                As[nxt][ac4[u] + 2][arow[u]] = avr[u].z;
                As[nxt][ac4[u] + 3][arow[u]] = avr[u].w;
            }
            #pragma unroll
            for (int u = 0; u < 2; u++)
                *(float4*)&Bs[nxt][brow[u]][bc4[u]] = bvr[u];
            __syncthreads();
        }
    }

    if (isQ) {
        #pragma unroll
        for (int ii = 0; ii < 8; ii++) {
            float2 p0 = unpack2(acc[ii][0]);
            float2 p1 = unpack2(acc[ii][1]);
            float2 p2 = unpack2(acc[ii][2]);
            float2 p3 = unpack2(acc[ii][3]);
            float* dst = g_qproj + (row0 + r0 + ii) * H_ + col0 + c0;
            *(float4*)dst       = make_float4(p0.x, p0.y, p1.x, p1.y);
            *(float4*)(dst + 4) = make_float4(p2.x, p2.y, p3.x, p3.y);
        }
    } else {
        float vals[8][8];
        #pragma unroll
        for (int ii = 0; ii < 8; ii++) {
            #pragma unroll
            for (int jp = 0; jp < 4; jp++) {
                float2 p = unpack2(acc[ii][jp]);
                vals[ii][jp * 2]     = p.x;
                vals[ii][jp * 2 + 1] = p.y;
            }
        }
        #pragma unroll
        for (int jj = 0; jj < 8; jj++) {
            long long n = col0 + c0 + jj;
            float* dst = g_kprojT + n * MK + row0 + r0;
            *(float4*)dst       = make_float4(vals[0][jj], vals[1][jj], vals[2][jj], vals[3][jj]);
            *(float4*)(dst + 4) = make_float4(vals[4][jj], vals[5][jj], vals[6][jj], vals[7][jj]);
        }
    }
}

// ----------------------------------------------------------------------------
// K2: masked tanh-scores, QT=8. grid = (16 q-tiles, 4 k-chunks, 8 b).
// Double-buffered staging of kprojT [16h][256k] tiles; thread owns one k.
// ----------------------------------------------------------------------------
__global__ __launch_bounds__(256)
void scores_kernel(const float* __restrict__ wv, const int* __restrict__ vlens)
{
    constexpr int QT = 8;
    constexpr int HC = 16;
    constexpr int NCH = H_ / HC;
    __shared__ float s_tile[2][HC][256];   // 32 KB
    __shared__ float s_q[QT][H_];          // 8 KB
    __shared__ float s_wv[H_];             // 1 KB

    const int b   = blockIdx.z;
    const int kp  = blockIdx.y;
    const int q0  = blockIdx.x * QT;
    const int tid = threadIdx.x;
    const int vlen = vlens[b];
    if (kp * 256 >= vlen) return;

    #pragma unroll
    for (int u = 0; u < QT; u++) {
        int i = u * 256 + tid;
        s_q[i >> 8][i & 255] =
            g_qproj[(long long)(b * Q_ + q0 + (i >> 8)) * H_ + (i & 255)];
    }
    if (tid < H_) s_wv[tid] = wv[tid];

    const float* kbase = g_kprojT + (long long)b * K_ + kp * 256;

    float4 rn[4];
    #pragma unroll
    for (int i = 0; i < 4; i++) {
        int idx = i * 256 + tid;
        int h = idx >> 6, c4 = (idx & 63) << 2;
        rn[i] = *(const float4*)(kbase + (long long)h * MK + c4);
    }
    #pragma unroll
    for (int i = 0; i < 4; i++) {
        int idx = i * 256 + tid;
        int h = idx >> 6, c4 = (idx & 63) << 2;
        *(float4*)&s_tile[0][h][c4] = rn[i];
    }
    __syncthreads();

    unsigned long long acc[QT];
    #pragma unroll
    for (int j = 0; j < QT; j++) acc[j] = 0ull;

    for (int hc = 0; hc < NCH; hc++) {
        const int cur = hc & 1;
        if (hc + 1 < NCH) {
            #pragma unroll
            for (int i = 0; i < 4; i++) {
                int idx = i * 256 + tid;
                int h = idx >> 6, c4 = (idx & 63) << 2;
                rn[i] = *(const float4*)(kbase + (long long)((hc + 1) * HC + h) * MK + c4);
            }
        }
        const int hbase = hc * HC;
        #pragma unroll
        for (int hh = 0; hh < HC; hh += 2) {
            float kv0 = s_tile[cur][hh][tid];
            float kv1 = s_tile[cur][hh + 1][tid];
            unsigned long long kvp = pack2(kv0, kv1);
            float2 w2 = *(const float2*)&s_wv[hbase + hh];
            unsigned long long wvp = pack2(w2.x, w2.y);
            #pragma unroll
            for (int j = 0; j < QT; j++) {
                float2 q2 = *(const float2*)&s_q[j][hbase + hh];
                float2 sf = unpack2(add2(pack2(q2.x, q2.y), kvp));
                unsigned long long t = pack2(tanh_fast(sf.x), tanh_fast(sf.y));
                acc[j] = fma2(t, wvp, acc[j]);
            }
        }
        if (hc + 1 < NCH) {
            #pragma unroll
            for (int i = 0; i < 4; i++) {
                int idx = i * 256 + tid;
                int h = idx >> 6, c4 = (idx & 63) << 2;
                *(float4*)&s_tile[1 - cur][h][c4] = rn[i];
            }
            __syncthreads();
        }
    }

    const int k = kp * 256 + tid;
    if (k < vlen) {
        #pragma unroll
        for (int j = 0; j < QT; j++) {
            float2 r = unpack2(acc[j]);
            g_scores[(long long)(b * Q_ + q0 + j) * K_ + k] = r.x + r.y;
        }
    }
}

// ----------------------------------------------------------------------------
// K3: masked softmax + AV. QT=8, warp-per-row softmax (no barriers inside),
// k-unroll 8 for MLP. grid = (16 q-tiles, 8 b), 256 threads.
// ----------------------------------------------------------------------------
__global__ __launch_bounds__(256)
void softmax_av(const int* __restrict__ vlens, const float* __restrict__ values,
                float* __restrict__ out)
{
    constexpr int QT = 8;
    __shared__ float s_sc[QT][K_];   // 32 KB
    __shared__ float s_inv[QT];

    const int b   = blockIdx.y;
    const int q0  = blockIdx.x * QT;
    const int tid = threadIdx.x;
    const int lane = tid & 31;
    const int wid  = tid >> 5;
    const int vlen = vlens[b];

    #pragma unroll
    for (int j = 0; j < QT; j++)
        for (int k = tid; k < vlen; k += 256)
            s_sc[j][k] = g_scores[(long long)(b * Q_ + q0 + j) * K_ + k];
    __syncthreads();

    // warp w owns row j = w
    {
        const int j = wid;
        float m = -3.4e38f;
        for (int k = lane; k < vlen; k += 32) m = fmaxf(m, s_sc[j][k]);
        #pragma unroll
        for (int off = 16; off; off >>= 1)
            m = fmaxf(m, __shfl_xor_sync(0xffffffffu, m, off));

        float s = 0.f;
        for (int k = lane; k < vlen; k += 32) {
            float e = __expf(s_sc[j][k] - m);
            s_sc[j][k] = e;
            s += e;
        }
        #pragma unroll
        for (int off = 16; off; off >>= 1)
            s += __shfl_xor_sync(0xffffffffu, s, off);
        if (lane == 0) s_inv[j] = 1.0f / s;
    }
    __syncthreads();

    float inv[QT];
    #pragma unroll
    for (int j = 0; j < QT; j++) inv[j] = s_inv[j];

    const int v0 = tid * 2;
    const float* vb = values + (long long)b * K_ * V_ + v0;
    unsigned long long acc[QT];
    #pragma unroll
    for (int j = 0; j < QT; j++) acc[j] = 0ull;

    int k = 0;
    #pragma unroll 1
    for (; k + 8 <= vlen; k += 8) {
        unsigned long long p[8];
        #pragma unroll
        for (int t = 0; t < 8; t++) {
            float2 vv = *(const float2*)(vb + (long long)(k + t) * V_);
            p[t] = pack2(vv.x, vv.y);
        }
        #pragma unroll
        for (int j = 0; j < QT; j++) {
            #pragma unroll
            for (int t = 0; t < 8; t++) {
                float e = s_sc[j][k + t];
                acc[j] = fma2(pack2(e, e), p[t], acc[j]);
            }
        }
    }
    for (; k < vlen; k++) {
        float2 vv = *(const float2*)(vb + (long long)k * V_);
        unsigned long long p = pack2(vv.x, vv.y);
        #pragma unroll
        for (int j = 0; j < QT; j++) {
            float e = s_sc[j][k];
            acc[j] = fma2(pack2(e, e), p, acc[j]);
        }
    }
    #pragma unroll
    for (int j = 0; j < QT; j++) {
        float2 r = unpack2(acc[j]);
        float2 o = make_float2(r.x * inv[j], r.y * inv[j]);
        *(float2*)(out + (long long)(b * Q_ + q0 + j) * V_ + v0) = o;
    }
}

// ----------------------------------------------------------------------------
extern "C" void kernel_launch(void* const* d_in, const int* in_sizes, int n_in,
                              void* d_out, int out_size)
{
    const float* queries = (const float*)d_in[0];  // [B,Q,D]
    const float* keys    = (const float*)d_in[1];  // [B,K,D]
    const float* values  = (const float*)d_in[2];  // [B,K,V]
    const int*   vlens   = (const int*)  d_in[3];  // [B]
    const float* Wq      = (const float*)d_in[4];  // [D,H]
    const float* Wk      = (const float*)d_in[5];  // [D,H]
    const float* wv      = (const float*)d_in[6];  // [H]
    float* out = (float*)d_out;                    // [B,Q,V]

    proj_gemm<<<dim3(H_ / 64, 8 + 64), 128>>>(queries, keys, Wq, Wk, vlens);
    scores_kernel<<<dim3(Q_ / 8, K_ / 256, B_), 256>>>(wv, vlens);
    softmax_av<<<dim3(Q_ / 8, B_), 256>>>(vlens, values, out);
}

// round 7
// speedup vs baseline: 1.1191x; 1.1191x over previous
#include <cuda_runtime.h>
#include <cstdint>

constexpr int B_ = 8;     // batch
constexpr int Q_ = 128;   // queries
constexpr int K_ = 1024;  // keys
constexpr int D_ = 512;   // qk feature dim
constexpr int H_ = 256;   // hidden
constexpr int V_ = 512;   // value dim
constexpr int MK = B_ * K_;   // 8192 rows of kproj

// Scratch (no cudaMalloc allowed)
__device__ float g_qproj [B_ * Q_ * H_];   // [B*Q][H]   1 MB
__device__ float g_kprojT[H_ * B_ * K_];   // [H][B*K]   8 MB (transposed)
__device__ float g_scores[B_ * Q_ * K_];   // [B*Q][K]   4 MB

__device__ __forceinline__ float tanh_fast(float x) {
    float y;
    asm("tanh.approx.f32 %0, %1;" : "=f"(y) : "f"(x));
    return y;
}
__device__ __forceinline__ unsigned long long pack2(float lo, float hi) {
    unsigned long long r;
    asm("mov.b64 %0, {%1, %2};" : "=l"(r) : "f"(lo), "f"(hi));
    return r;
}
__device__ __forceinline__ float2 unpack2(unsigned long long v) {
    float2 r;
    asm("mov.b64 {%0, %1}, %2;" : "=f"(r.x), "=f"(r.y) : "l"(v));
    return r;
}
__device__ __forceinline__ unsigned long long fma2(unsigned long long a,
                                                   unsigned long long b,
                                                   unsigned long long c) {
    unsigned long long d;
    asm("fma.rn.f32x2 %0, %1, %2, %3;" : "=l"(d) : "l"(a), "l"(b), "l"(c));
    return d;
}
__device__ __forceinline__ unsigned long long add2(unsigned long long a,
                                                   unsigned long long b) {
    unsigned long long d;
    asm("add.rn.f32x2 %0, %1, %2;" : "=l"(d) : "l"(a), "l"(b));
    return d;
}

// ----------------------------------------------------------------------------
// K1: merged projection GEMM v4.
// 128x64 tile, BK=16, 256 threads, 8x4 microtile (32 acc regs — no spill),
// double-buffered smem, masked early-exit on kproj tiles.
//   blockIdx.y <  8 : qproj row tile -> g_qproj  [B*Q][H]
//   blockIdx.y >= 8 : kproj row tile -> g_kprojT [H][B*K] (transposed)
// ----------------------------------------------------------------------------
__global__ __launch_bounds__(256)
void proj_gemm(const float* __restrict__ queries, const float* __restrict__ keys,
               const float* __restrict__ Wq, const float* __restrict__ Wk,
               const int* __restrict__ vlens)
{
    constexpr int BM = 128, BN = 64, BK = 16;
    __shared__ float As[2][BK][BM + 4];
    __shared__ float Bs[2][BK][BN];

    const int tid = threadIdx.x;
    const bool isQ = (blockIdx.y < 8);
    const float* A;
    const float* W;
    long long row0;
    if (isQ) {
        A = queries; W = Wq; row0 = (long long)blockIdx.y * BM;
    } else {
        int r  = (int)(blockIdx.y - 8) * BM;
        int b  = r >> 10;
        int k0 = r & 1023;
        if (k0 >= vlens[b]) return;     // masked kproj tile
        A = keys; W = Wk; row0 = r;
    }
    const int col0 = blockIdx.x * BN;

    const int ty = tid >> 4, tx = tid & 15;   // 16x16 thread grid
    const int r0 = ty * 8, c0 = tx * 4;

    // loader mappings: A 128x16 -> 2 float4/thread; B 16x64 -> 1 float4/thread
    int arow[2], ac4[2];
    #pragma unroll
    for (int u = 0; u < 2; u++) {
        int l = tid * 2 + u;
        arow[u] = l >> 2;  ac4[u] = (l & 3) << 2;
    }
    const int brow = tid >> 4, bc4 = (tid & 15) << 2;

    unsigned long long acc[8][2];
    #pragma unroll
    for (int i = 0; i < 8; i++) { acc[i][0] = 0ull; acc[i][1] = 0ull; }

    float4 avr[2], bvr;
    #pragma unroll
    for (int u = 0; u < 2; u++)
        avr[u] = *(const float4*)(A + (row0 + arow[u]) * D_ + ac4[u]);
    bvr = *(const float4*)(W + (long long)brow * H_ + col0 + bc4);
    #pragma unroll
    for (int u = 0; u < 2; u++) {
        As[0][ac4[u] + 0][arow[u]] = avr[u].x;
        As[0][ac4[u] + 1][arow[u]] = avr[u].y;
        As[0][ac4[u] + 2][arow[u]] = avr[u].z;
        As[0][ac4[u] + 3][arow[u]] = avr[u].w;
    }
    *(float4*)&Bs[0][brow][bc4] = bvr;
    __syncthreads();

    constexpr int NKB = D_ / BK;   // 32
    for (int it = 0; it < NKB; it++) {
        const int cur = it & 1;
        if (it + 1 < NKB) {
            const int kb = (it + 1) * BK;
            #pragma unroll
            for (int u = 0; u < 2; u++)
                avr[u] = *(const float4*)(A + (row0 + arow[u]) * D_ + kb + ac4[u]);
            bvr = *(const float4*)(W + (long long)(kb + brow) * H_ + col0 + bc4);
        }
        #pragma unroll
        for (int kk = 0; kk < BK; kk++) {
            float4 a0 = *(const float4*)&As[cur][kk][r0];
            float4 a1 = *(const float4*)&As[cur][kk][r0 + 4];
            float4 bq = *(const float4*)&Bs[cur][kk][c0];
            unsigned long long b01 = pack2(bq.x, bq.y);
            unsigned long long b23 = pack2(bq.z, bq.w);
            float a[8] = {a0.x, a0.y, a0.z, a0.w, a1.x, a1.y, a1.z, a1.w};
            #pragma unroll
            for (int ii = 0; ii < 8; ii++) {
                unsigned long long a2 = pack2(a[ii], a[ii]);
                acc[ii][0] = fma2(a2, b01, acc[ii][0]);
                acc[ii][1] = fma2(a2, b23, acc[ii][1]);
            }
        }
        if (it + 1 < NKB) {
            const int nxt = 1 - cur;
            #pragma unroll
            for (int u = 0; u < 2; u++) {
                As[nxt][ac4[u] + 0][arow[u]] = avr[u].x;
                As[nxt][ac4[u] + 1][arow[u]] = avr[u].y;
                As[nxt][ac4[u] + 2][arow[u]] = avr[u].z;
                As[nxt][ac4[u] + 3][arow[u]] = avr[u].w;
            }
            *(float4*)&Bs[nxt][brow][bc4] = bvr;
            __syncthreads();
        }
    }

    if (isQ) {
        #pragma unroll
        for (int ii = 0; ii < 8; ii++) {
            float2 lo = unpack2(acc[ii][0]);
            float2 hi = unpack2(acc[ii][1]);
            *(float4*)(g_qproj + (row0 + r0 + ii) * H_ + col0 + c0) =
                make_float4(lo.x, lo.y, hi.x, hi.y);
        }
    } else {
        float vals[8][4];
        #pragma unroll
        for (int ii = 0; ii < 8; ii++) {
            float2 lo = unpack2(acc[ii][0]);
            float2 hi = unpack2(acc[ii][1]);
            vals[ii][0] = lo.x; vals[ii][1] = lo.y;
            vals[ii][2] = hi.x; vals[ii][3] = hi.y;
        }
        #pragma unroll
        for (int jj = 0; jj < 4; jj++) {
            long long n = col0 + c0 + jj;
            float* dst = g_kprojT + n * MK + row0 + r0;
            *(float4*)dst       = make_float4(vals[0][jj], vals[1][jj], vals[2][jj], vals[3][jj]);
            *(float4*)(dst + 4) = make_float4(vals[4][jj], vals[5][jj], vals[6][jj], vals[7][jj]);
        }
    }
}

// ----------------------------------------------------------------------------
// K2: masked tanh-scores, QT=4 (round-4 version — known good).
// grid = (32 q-tiles, 4 k-chunks, 8 b), 256 threads.
// ----------------------------------------------------------------------------
__global__ __launch_bounds__(256)
void scores_kernel(const float* __restrict__ wv, const int* __restrict__ vlens)
{
    constexpr int QT = 4;
    constexpr int HC = 16;
    constexpr int NCH = H_ / HC;
    __shared__ float s_tile[2][HC][256];
    __shared__ float s_q[QT][H_];
    __shared__ float s_wv[H_];

    const int b   = blockIdx.z;
    const int kp  = blockIdx.y;
    const int q0  = blockIdx.x * QT;
    const int tid = threadIdx.x;
    const int vlen = vlens[b];
    if (kp * 256 >= vlen) return;

    for (int i = tid; i < QT * H_; i += 256)
        s_q[i >> 8][i & 255] = g_qproj[(long long)(b * Q_ + q0 + (i >> 8)) * H_ + (i & 255)];
    for (int i = tid; i < H_; i += 256) s_wv[i] = wv[i];

    const float* kbase = g_kprojT + (long long)b * K_ + kp * 256;

    float4 rn[4];
    #pragma unroll
    for (int i = 0; i < 4; i++) {
        int idx = i * 256 + tid;
        int h = idx >> 6, c4 = (idx & 63) << 2;
        rn[i] = *(const float4*)(kbase + (long long)h * MK + c4);
    }
    #pragma unroll
    for (int i = 0; i < 4; i++) {
        int idx = i * 256 + tid;
        int h = idx >> 6, c4 = (idx & 63) << 2;
        *(float4*)&s_tile[0][h][c4] = rn[i];
    }
    __syncthreads();

    unsigned long long acc[QT] = {0ull, 0ull, 0ull, 0ull};

    for (int hc = 0; hc < NCH; hc++) {
        const int cur = hc & 1;
        if (hc + 1 < NCH) {
            #pragma unroll
            for (int i = 0; i < 4; i++) {
                int idx = i * 256 + tid;
                int h = idx >> 6, c4 = (idx & 63) << 2;
                rn[i] = *(const float4*)(kbase + (long long)((hc + 1) * HC + h) * MK + c4);
            }
        }
        const int hbase = hc * HC;
        #pragma unroll
        for (int hh = 0; hh < HC; hh += 2) {
            float kv0 = s_tile[cur][hh][tid];
            float kv1 = s_tile[cur][hh + 1][tid];
            unsigned long long kvp = pack2(kv0, kv1);
            float2 w2 = *(const float2*)&s_wv[hbase + hh];
            unsigned long long wvp = pack2(w2.x, w2.y);
            #pragma unroll
            for (int j = 0; j < QT; j++) {
                float2 q2 = *(const float2*)&s_q[j][hbase + hh];
                float2 sf = unpack2(add2(pack2(q2.x, q2.y), kvp));
                unsigned long long t = pack2(tanh_fast(sf.x), tanh_fast(sf.y));
                acc[j] = fma2(t, wvp, acc[j]);
            }
        }
        if (hc + 1 < NCH) {
            #pragma unroll
            for (int i = 0; i < 4; i++) {
                int idx = i * 256 + tid;
                int h = idx >> 6, c4 = (idx & 63) << 2;
                *(float4*)&s_tile[1 - cur][h][c4] = rn[i];
            }
            __syncthreads();
        }
    }

    const int k = kp * 256 + tid;
    if (k < vlen) {
        #pragma unroll
        for (int j = 0; j < QT; j++) {
            float2 r = unpack2(acc[j]);
            g_scores[(long long)(b * Q_ + q0 + j) * K_ + k] = r.x + r.y;
        }
    }
}

// ----------------------------------------------------------------------------
// K3: masked softmax + AV. QT=8, k-unroll 8 (round-4 version — known good).
// grid = (16 q-tiles, 8 b), 256 threads.
// ----------------------------------------------------------------------------
__global__ __launch_bounds__(256)
void softmax_av(const int* __restrict__ vlens, const float* __restrict__ values,
                float* __restrict__ out)
{
    constexpr int QT = 8;
    __shared__ float s_sc[QT][K_];   // 32 KB
    __shared__ float s_red[8];

    const int b   = blockIdx.y;
    const int q0  = blockIdx.x * QT;
    const int tid = threadIdx.x;
    const int lane = tid & 31;
    const int wid  = tid >> 5;
    const int vlen = vlens[b];

    #pragma unroll
    for (int j = 0; j < QT; j++)
        for (int k = tid; k < vlen; k += 256)
            s_sc[j][k] = g_scores[(long long)(b * Q_ + q0 + j) * K_ + k];
    __syncthreads();

    float inv[QT];
    #pragma unroll 1
    for (int j = 0; j < QT; j++) {
        float m = -3.4e38f;
        for (int k = tid; k < vlen; k += 256) m = fmaxf(m, s_sc[j][k]);
        #pragma unroll
        for (int off = 16; off; off >>= 1)
            m = fmaxf(m, __shfl_xor_sync(0xffffffffu, m, off));
        if (lane == 0) s_red[wid] = m;
        __syncthreads();
        float mm = s_red[0];
        #pragma unroll
        for (int w = 1; w < 8; w++) mm = fmaxf(mm, s_red[w]);
        __syncthreads();

        float s = 0.f;
        for (int k = tid; k < vlen; k += 256) {
            float e = __expf(s_sc[j][k] - mm);
            s_sc[j][k] = e;
            s += e;
        }
        #pragma unroll
        for (int off = 16; off; off >>= 1)
            s += __shfl_xor_sync(0xffffffffu, s, off);
        if (lane == 0) s_red[wid] = s;
        __syncthreads();
        float ssum = 0.f;
        #pragma unroll
        for (int w = 0; w < 8; w++) ssum += s_red[w];
        inv[j] = 1.0f / ssum;
        __syncthreads();
    }

    const int v0 = tid * 2;
    const float* vb = values + (long long)b * K_ * V_ + v0;
    unsigned long long acc[QT];
    #pragma unroll
    for (int j = 0; j < QT; j++) acc[j] = 0ull;

    int k = 0;
    #pragma unroll 1
    for (; k + 8 <= vlen; k += 8) {
        unsigned long long p[8];
        #pragma unroll
        for (int t = 0; t < 8; t++) {
            float2 vv = *(const float2*)(vb + (long long)(k + t) * V_);
            p[t] = pack2(vv.x, vv.y);
        }
        #pragma unroll
        for (int j = 0; j < QT; j++) {
            #pragma unroll
            for (int t = 0; t < 8; t++) {
                float e = s_sc[j][k + t];
                acc[j] = fma2(pack2(e, e), p[t], acc[j]);
            }
        }
    }
    for (; k < vlen; k++) {
        float2 vv = *(const float2*)(vb + (long long)k * V_);
        unsigned long long p = pack2(vv.x, vv.y);
        #pragma unroll
        for (int j = 0; j < QT; j++) {
            float e = s_sc[j][k];
            acc[j] = fma2(pack2(e, e), p, acc[j]);
        }
    }
    #pragma unroll
    for (int j = 0; j < QT; j++) {
        float2 r = unpack2(acc[j]);
        float2 o = make_float2(r.x * inv[j], r.y * inv[j]);
        *(float2*)(out + (long long)(b * Q_ + q0 + j) * V_ + v0) = o;
    }
}

// ----------------------------------------------------------------------------
extern "C" void kernel_launch(void* const* d_in, const int* in_sizes, int n_in,
                              void* d_out, int out_size)
{
    const float* queries = (const float*)d_in[0];  // [B,Q,D]
    const float* keys    = (const float*)d_in[1];  // [B,K,D]
    const float* values  = (const float*)d_in[2];  // [B,K,V]
    const int*   vlens   = (const int*)  d_in[3];  // [B]
    const float* Wq      = (const float*)d_in[4];  // [D,H]
    const float* Wk      = (const float*)d_in[5];  // [D,H]
    const float* wv      = (const float*)d_in[6];  // [H]
    float* out = (float*)d_out;                    // [B,Q,V]

    proj_gemm<<<dim3(H_ / 64, 8 + 64), 256>>>(queries, keys, Wq, Wk, vlens);
    scores_kernel<<<dim3(Q_ / 4, K_ / 256, B_), 256>>>(wv, vlens);
    softmax_av<<<dim3(Q_ / 8, B_), 256>>>(vlens, values, out);
}

// round 8
// speedup vs baseline: 1.3621x; 1.2172x over previous
#include <cuda_runtime.h>
#include <cstdint>

constexpr int B_ = 8;     // batch
constexpr int Q_ = 128;   // queries
constexpr int K_ = 1024;  // keys
constexpr int D_ = 512;   // qk feature dim
constexpr int H_ = 256;   // hidden
constexpr int V_ = 512;   // value dim
constexpr int MK = B_ * K_;   // 8192 rows of kproj

// Scratch (no cudaMalloc allowed)
__device__ float g_qproj [B_ * Q_ * H_];   // [B*Q][H]   1 MB
__device__ float g_kprojT[H_ * B_ * K_];   // [H][B*K]   8 MB (transposed)
__device__ float g_scores[B_ * Q_ * K_];   // [B*Q][K]   4 MB

__device__ __forceinline__ float tanh_fast(float x) {
    float y;
    asm("tanh.approx.f32 %0, %1;" : "=f"(y) : "f"(x));
    return y;
}
__device__ __forceinline__ unsigned long long pack2(float lo, float hi) {
    unsigned long long r;
    asm("mov.b64 %0, {%1, %2};" : "=l"(r) : "f"(lo), "f"(hi));
    return r;
}
__device__ __forceinline__ float2 unpack2(unsigned long long v) {
    float2 r;
    asm("mov.b64 {%0, %1}, %2;" : "=f"(r.x), "=f"(r.y) : "l"(v));
    return r;
}
__device__ __forceinline__ unsigned long long fma2(unsigned long long a,
                                                   unsigned long long b,
                                                   unsigned long long c) {
    unsigned long long d;
    asm("fma.rn.f32x2 %0, %1, %2, %3;" : "=l"(d) : "l"(a), "l"(b), "l"(c));
    return d;
}
__device__ __forceinline__ unsigned long long add2(unsigned long long a,
                                                   unsigned long long b) {
    unsigned long long d;
    asm("add.rn.f32x2 %0, %1, %2;" : "=l"(d) : "l"(a), "l"(b));
    return d;
}

// ----------------------------------------------------------------------------
// K1: merged projection GEMM v5.
// 64x64 tile, BK=16, 128 threads, ROW-PAIRED 8x4 microtile:
//   acc[rp][j] = f32x2 over rows (2rp, 2rp+1), column j.
//   A row-pairs come straight from LDS.64 (no dup movs); only 4 b-dup movs/kk.
// Double-buffered smem, masked early-exit on kproj tiles.
// ----------------------------------------------------------------------------
__global__ __launch_bounds__(128)
void proj_gemm(const float* __restrict__ queries, const float* __restrict__ keys,
               const float* __restrict__ Wq, const float* __restrict__ Wk,
               const int* __restrict__ vlens)
{
    __shared__ float As[2][16][68];
    __shared__ float Bs[2][16][64];

    const int tid = threadIdx.x;
    const bool isQ = (blockIdx.y < 16);
    const float* A;
    const float* W;
    long long row0;
    if (isQ) {
        A = queries; W = Wq; row0 = (long long)blockIdx.y * 64;
    } else {
        int r  = (int)(blockIdx.y - 16) * 64;
        int b  = r >> 10;
        int k0 = r & 1023;
        if (k0 >= vlens[b]) return;     // masked kproj tile
        A = keys; W = Wk; row0 = r;
    }
    const int col0 = blockIdx.x * 64;

    const int ty = tid >> 4, tx = tid & 15;
    const int r0 = ty * 8, tn = tx * 4;

    int arow[2], ac4[2], brow[2], bc4[2];
    #pragma unroll
    for (int u = 0; u < 2; u++) {
        int l = tid * 2 + u;
        arow[u] = l >> 2;  ac4[u] = (l & 3) << 2;
        brow[u] = l >> 4;  bc4[u] = (l & 15) << 2;
    }

    // acc[rp][j]: row-pair rp (rows r0+2rp, r0+2rp+1), col tn+j
    unsigned long long acc[4][4];
    #pragma unroll
    for (int i = 0; i < 4; i++)
        #pragma unroll
        for (int j = 0; j < 4; j++) acc[i][j] = 0ull;

    float4 avr[2], bvr[2];
    #pragma unroll
    for (int u = 0; u < 2; u++) {
        avr[u] = *(const float4*)(A + (row0 + arow[u]) * D_ + ac4[u]);
        bvr[u] = *(const float4*)(W + (long long)brow[u] * H_ + col0 + bc4[u]);
    }
    #pragma unroll
    for (int u = 0; u < 2; u++) {
        As[0][ac4[u] + 0][arow[u]] = avr[u].x;
        As[0][ac4[u] + 1][arow[u]] = avr[u].y;
        As[0][ac4[u] + 2][arow[u]] = avr[u].z;
        As[0][ac4[u] + 3][arow[u]] = avr[u].w;
        *(float4*)&Bs[0][brow[u]][bc4[u]] = bvr[u];
    }
    __syncthreads();

    constexpr int NKB = D_ / 16;   // 32
    for (int it = 0; it < NKB; it++) {
        const int cur = it & 1;
        if (it + 1 < NKB) {
            const int kb = (it + 1) * 16;
            #pragma unroll
            for (int u = 0; u < 2; u++) {
                avr[u] = *(const float4*)(A + (row0 + arow[u]) * D_ + kb + ac4[u]);
                bvr[u] = *(const float4*)(W + (long long)(kb + brow[u]) * H_ + col0 + bc4[u]);
            }
        }
        #pragma unroll
        for (int kk = 0; kk < 16; kk++) {
            // row-pairs directly as 64-bit LDS (no dup movs)
            unsigned long long ap[4];
            #pragma unroll
            for (int rp = 0; rp < 4; rp++)
                ap[rp] = *(const unsigned long long*)&As[cur][kk][r0 + 2 * rp];
            float4 bq = *(const float4*)&Bs[cur][kk][tn];
            unsigned long long bd[4] = {pack2(bq.x, bq.x), pack2(bq.y, bq.y),
                                        pack2(bq.z, bq.z), pack2(bq.w, bq.w)};
            #pragma unroll
            for (int rp = 0; rp < 4; rp++) {
                #pragma unroll
                for (int j = 0; j < 4; j++)
                    acc[rp][j] = fma2(ap[rp], bd[j], acc[rp][j]);
            }
        }
        if (it + 1 < NKB) {
            const int nxt = 1 - cur;
            #pragma unroll
            for (int u = 0; u < 2; u++) {
                As[nxt][ac4[u] + 0][arow[u]] = avr[u].x;
                As[nxt][ac4[u] + 1][arow[u]] = avr[u].y;
                As[nxt][ac4[u] + 2][arow[u]] = avr[u].z;
                As[nxt][ac4[u] + 3][arow[u]] = avr[u].w;
                *(float4*)&Bs[nxt][brow[u]][bc4[u]] = bvr[u];
            }
            __syncthreads();
        }
    }

    if (isQ) {
        #pragma unroll
        for (int rp = 0; rp < 4; rp++) {
            float2 c0 = unpack2(acc[rp][0]);
            float2 c1 = unpack2(acc[rp][1]);
            float2 c2 = unpack2(acc[rp][2]);
            float2 c3 = unpack2(acc[rp][3]);
            float* d0 = g_qproj + (row0 + r0 + 2 * rp)     * H_ + col0 + tn;
            float* d1 = g_qproj + (row0 + r0 + 2 * rp + 1) * H_ + col0 + tn;
            *(float4*)d0 = make_float4(c0.x, c1.x, c2.x, c3.x);
            *(float4*)d1 = make_float4(c0.y, c1.y, c2.y, c3.y);
        }
    } else {
        // transposed: column n = col0+tn+j owns rows r0..r0+7 contiguously
        #pragma unroll
        for (int j = 0; j < 4; j++) {
            float2 p0 = unpack2(acc[0][j]);
            float2 p1 = unpack2(acc[1][j]);
            float2 p2 = unpack2(acc[2][j]);
            float2 p3 = unpack2(acc[3][j]);
            long long n = col0 + tn + j;
            float* dst = g_kprojT + n * MK + row0 + r0;
            *(float4*)dst       = make_float4(p0.x, p0.y, p1.x, p1.y);
            *(float4*)(dst + 4) = make_float4(p2.x, p2.y, p3.x, p3.y);
        }
    }
}

// ----------------------------------------------------------------------------
// K2: masked tanh-scores, QT=4 (unchanged — near MUFU floor).
// grid = (32 q-tiles, 4 k-chunks, 8 b), 256 threads.
// ----------------------------------------------------------------------------
__global__ __launch_bounds__(256)
void scores_kernel(const float* __restrict__ wv, const int* __restrict__ vlens)
{
    constexpr int QT = 4;
    constexpr int HC = 16;
    constexpr int NCH = H_ / HC;
    __shared__ float s_tile[2][HC][256];
    __shared__ float s_q[QT][H_];
    __shared__ float s_wv[H_];

    const int b   = blockIdx.z;
    const int kp  = blockIdx.y;
    const int q0  = blockIdx.x * QT;
    const int tid = threadIdx.x;
    const int vlen = vlens[b];
    if (kp * 256 >= vlen) return;

    for (int i = tid; i < QT * H_; i += 256)
        s_q[i >> 8][i & 255] = g_qproj[(long long)(b * Q_ + q0 + (i >> 8)) * H_ + (i & 255)];
    for (int i = tid; i < H_; i += 256) s_wv[i] = wv[i];

    const float* kbase = g_kprojT + (long long)b * K_ + kp * 256;

    float4 rn[4];
    #pragma unroll
    for (int i = 0; i < 4; i++) {
        int idx = i * 256 + tid;
        int h = idx >> 6, c4 = (idx & 63) << 2;
        rn[i] = *(const float4*)(kbase + (long long)h * MK + c4);
    }
    #pragma unroll
    for (int i = 0; i < 4; i++) {
        int idx = i * 256 + tid;
        int h = idx >> 6, c4 = (idx & 63) << 2;
        *(float4*)&s_tile[0][h][c4] = rn[i];
    }
    __syncthreads();

    unsigned long long acc[QT] = {0ull, 0ull, 0ull, 0ull};

    for (int hc = 0; hc < NCH; hc++) {
        const int cur = hc & 1;
        if (hc + 1 < NCH) {
            #pragma unroll
            for (int i = 0; i < 4; i++) {
                int idx = i * 256 + tid;
                int h = idx >> 6, c4 = (idx & 63) << 2;
                rn[i] = *(const float4*)(kbase + (long long)((hc + 1) * HC + h) * MK + c4);
            }
        }
        const int hbase = hc * HC;
        #pragma unroll
        for (int hh = 0; hh < HC; hh += 2) {
            float kv0 = s_tile[cur][hh][tid];
            float kv1 = s_tile[cur][hh + 1][tid];
            unsigned long long kvp = pack2(kv0, kv1);
            float2 w2 = *(const float2*)&s_wv[hbase + hh];
            unsigned long long wvp = pack2(w2.x, w2.y);
            #pragma unroll
            for (int j = 0; j < QT; j++) {
                float2 q2 = *(const float2*)&s_q[j][hbase + hh];
                float2 sf = unpack2(add2(pack2(q2.x, q2.y), kvp));
                unsigned long long t = pack2(tanh_fast(sf.x), tanh_fast(sf.y));
                acc[j] = fma2(t, wvp, acc[j]);
            }
        }
        if (hc + 1 < NCH) {
            #pragma unroll
            for (int i = 0; i < 4; i++) {
                int idx = i * 256 + tid;
                int h = idx >> 6, c4 = (idx & 63) << 2;
                *(float4*)&s_tile[1 - cur][h][c4] = rn[i];
            }
            __syncthreads();
        }
    }

    const int k = kp * 256 + tid;
    if (k < vlen) {
        #pragma unroll
        for (int j = 0; j < QT; j++) {
            float2 r = unpack2(acc[j]);
            g_scores[(long long)(b * Q_ + q0 + j) * K_ + k] = r.x + r.y;
        }
    }
}

// ----------------------------------------------------------------------------
// K3: masked softmax + AV. QT=4 (round-4 measured-good version).
// grid = (32 q-tiles, 8 b), 256 threads.
// ----------------------------------------------------------------------------
__global__ __launch_bounds__(256)
void softmax_av(const int* __restrict__ vlens, const float* __restrict__ values,
                float* __restrict__ out)
{
    constexpr int QT = 4;
    __shared__ float s_sc[QT][K_];   // 16 KB
    __shared__ float s_red[8];

    const int b   = blockIdx.y;
    const int q0  = blockIdx.x * QT;
    const int tid = threadIdx.x;
    const int lane = tid & 31;
    const int wid  = tid >> 5;
    const int vlen = vlens[b];

    #pragma unroll
    for (int j = 0; j < QT; j++)
        for (int k = tid; k < vlen; k += 256)
            s_sc[j][k] = g_scores[(long long)(b * Q_ + q0 + j) * K_ + k];
    __syncthreads();

    float inv[QT];
    #pragma unroll 1
    for (int j = 0; j < QT; j++) {
        float m = -3.4e38f;
        for (int k = tid; k < vlen; k += 256) m = fmaxf(m, s_sc[j][k]);
        #pragma unroll
        for (int off = 16; off; off >>= 1)
            m = fmaxf(m, __shfl_xor_sync(0xffffffffu, m, off));
        if (lane == 0) s_red[wid] = m;
        __syncthreads();
        float mm = s_red[0];
        #pragma unroll
        for (int w = 1; w < 8; w++) mm = fmaxf(mm, s_red[w]);
        __syncthreads();

        float s = 0.f;
        for (int k = tid; k < vlen; k += 256) {
            float e = __expf(s_sc[j][k] - mm);
            s_sc[j][k] = e;
            s += e;
        }
        #pragma unroll
        for (int off = 16; off; off >>= 1)
            s += __shfl_xor_sync(0xffffffffu, s, off);
        if (lane == 0) s_red[wid] = s;
        __syncthreads();
        float ssum = 0.f;
        #pragma unroll
        for (int w = 0; w < 8; w++) ssum += s_red[w];
        inv[j] = 1.0f / ssum;
        __syncthreads();
    }

    const int v0 = tid * 2;
    const float* vb = values + (long long)b * K_ * V_ + v0;
    unsigned long long acc[QT] = {0ull, 0ull, 0ull, 0ull};
    int k = 0;
    #pragma unroll 1
    for (; k + 4 <= vlen; k += 4) {
        float2 vv0 = *(const float2*)(vb + (long long)(k + 0) * V_);
        float2 vv1 = *(const float2*)(vb + (long long)(k + 1) * V_);
        float2 vv2 = *(const float2*)(vb + (long long)(k + 2) * V_);
        float2 vv3 = *(const float2*)(vb + (long long)(k + 3) * V_);
        unsigned long long p0 = pack2(vv0.x, vv0.y);
        unsigned long long p1 = pack2(vv1.x, vv1.y);
        unsigned long long p2 = pack2(vv2.x, vv2.y);
        unsigned long long p3 = pack2(vv3.x, vv3.y);
        #pragma unroll
        for (int j = 0; j < QT; j++) {
            float e0 = s_sc[j][k], e1 = s_sc[j][k + 1];
            float e2 = s_sc[j][k + 2], e3 = s_sc[j][k + 3];
            acc[j] = fma2(pack2(e0, e0), p0, acc[j]);
            acc[j] = fma2(pack2(e1, e1), p1, acc[j]);
            acc[j] = fma2(pack2(e2, e2), p2, acc[j]);
            acc[j] = fma2(pack2(e3, e3), p3, acc[j]);
        }
    }
    for (; k < vlen; k++) {
        float2 vv = *(const float2*)(vb + (long long)k * V_);
        unsigned long long p = pack2(vv.x, vv.y);
        #pragma unroll
        for (int j = 0; j < QT; j++) {
            float e = s_sc[j][k];
            acc[j] = fma2(pack2(e, e), p, acc[j]);
        }
    }
    #pragma unroll
    for (int j = 0; j < QT; j++) {
        float2 r = unpack2(acc[j]);
        float2 o = make_float2(r.x * inv[j], r.y * inv[j]);
        *(float2*)(out + (long long)(b * Q_ + q0 + j) * V_ + v0) = o;
    }
}

// ----------------------------------------------------------------------------
extern "C" void kernel_launch(void* const* d_in, const int* in_sizes, int n_in,
                              void* d_out, int out_size)
{
    const float* queries = (const float*)d_in[0];  // [B,Q,D]
    const float* keys    = (const float*)d_in[1];  // [B,K,D]
    const float* values  = (const float*)d_in[2];  // [B,K,V]
    const int*   vlens   = (const int*)  d_in[3];  // [B]
    const float* Wq      = (const float*)d_in[4];  // [D,H]
    const float* Wk      = (const float*)d_in[5];  // [D,H]
    const float* wv      = (const float*)d_in[6];  // [H]
    float* out = (float*)d_out;                    // [B,Q,V]

    proj_gemm<<<dim3(H_ / 64, 16 + 128), 128>>>(queries, keys, Wq, Wk, vlens);
    scores_kernel<<<dim3(Q_ / 4, K_ / 256, B_), 256>>>(wv, vlens);
    softmax_av<<<dim3(Q_ / 4, B_), 256>>>(vlens, values, out);
}

// round 9
// speedup vs baseline: 1.4449x; 1.0608x over previous
#include <cuda_runtime.h>
#include <cstdint>

constexpr int B_ = 8;     // batch
constexpr int Q_ = 128;   // queries
constexpr int K_ = 1024;  // keys
constexpr int D_ = 512;   // qk feature dim
constexpr int H_ = 256;   // hidden
constexpr int V_ = 512;   // value dim
constexpr int MK = B_ * K_;   // 8192 rows of kproj

// Scratch (no cudaMalloc allowed)
__device__ float g_qproj [B_ * Q_ * H_];   // [B*Q][H]   1 MB
__device__ float g_kprojT[H_ * B_ * K_];   // [H][B*K]   8 MB (transposed)
__device__ float g_scores[B_ * Q_ * K_];   // [B*Q][K]   4 MB

__device__ __forceinline__ float tanh_fast(float x) {
    float y;
    asm("tanh.approx.f32 %0, %1;" : "=f"(y) : "f"(x));
    return y;
}
__device__ __forceinline__ unsigned long long pack2(float lo, float hi) {
    unsigned long long r;
    asm("mov.b64 %0, {%1, %2};" : "=l"(r) : "f"(lo), "f"(hi));
    return r;
}
__device__ __forceinline__ float2 unpack2(unsigned long long v) {
    float2 r;
    asm("mov.b64 {%0, %1}, %2;" : "=f"(r.x), "=f"(r.y) : "l"(v));
    return r;
}
__device__ __forceinline__ unsigned long long fma2(unsigned long long a,
                                                   unsigned long long b,
                                                   unsigned long long c) {
    unsigned long long d;
    asm("fma.rn.f32x2 %0, %1, %2, %3;" : "=l"(d) : "l"(a), "l"(b), "l"(c));
    return d;
}
__device__ __forceinline__ unsigned long long add2(unsigned long long a,
                                                   unsigned long long b) {
    unsigned long long d;
    asm("add.rn.f32x2 %0, %1, %2;" : "=l"(d) : "l"(a), "l"(b));
    return d;
}
__device__ __forceinline__ uint32_t f2tf32(float x) {
    uint32_t r;
    asm("cvt.rna.tf32.f32 %0, %1;" : "=r"(r) : "f"(x));
    return r;
}
__device__ __forceinline__ void mma_tf32(float* c, const uint32_t* a, const uint32_t* b) {
    asm volatile(
        "mma.sync.aligned.m16n8k8.row.col.f32.tf32.tf32.f32 "
        "{%0,%1,%2,%3}, {%4,%5,%6,%7}, {%8,%9}, {%0,%1,%2,%3};"
        : "+f"(c[0]), "+f"(c[1]), "+f"(c[2]), "+f"(c[3])
        : "r"(a[0]), "r"(a[1]), "r"(a[2]), "r"(a[3]), "r"(b[0]), "r"(b[1]));
}

// ----------------------------------------------------------------------------
// K1: tensor-core projection GEMM (tf32 HMMA, A hi/lo split for precision).
// 64x64 tile, BK=16, 128 threads = 2x2 warps, each warp 32x32 via m16n8k8.
// smem [k][m]/[k][n] stride-72 (bank-conflict-free fragment gathers).
// Double-buffered; masked early-exit on kproj tiles.
//   blockIdx.y <  16 : qproj row tile -> g_qproj  [B*Q][H]
//   blockIdx.y >= 16 : kproj row tile -> g_kprojT [H][B*K] (transposed)
// ----------------------------------------------------------------------------
__global__ __launch_bounds__(128)
void proj_gemm(const float* __restrict__ queries, const float* __restrict__ keys,
               const float* __restrict__ Wq, const float* __restrict__ Wk,
               const int* __restrict__ vlens)
{
    constexpr int BK = 16, PAD = 72;
    __shared__ uint32_t AsHi[2][BK][PAD];
    __shared__ uint32_t AsLo[2][BK][PAD];
    __shared__ uint32_t Bsm [2][BK][PAD];

    const int tid = threadIdx.x;
    const bool isQ = (blockIdx.y < 16);
    const float* A;
    const float* W;
    long long row0;
    if (isQ) {
        A = queries; W = Wq; row0 = (long long)blockIdx.y * 64;
    } else {
        int r  = (int)(blockIdx.y - 16) * 64;
        int b  = r >> 10;
        int k0 = r & 1023;
        if (k0 >= vlens[b]) return;     // masked kproj tile
        A = keys; W = Wk; row0 = r;
    }
    const int col0 = blockIdx.x * 64;

    const int warp = tid >> 5, lane = tid & 31;
    const int wm = warp >> 1, wn = warp & 1;        // 2x2 warp grid
    const int gid = lane >> 2, titg = lane & 3;     // fragment coords
    const int m_base = wm * 32;                     // + mt*16
    const int n_base = wn * 32;                     // + nt*8

    // loader mappings: A tile 64x16 (2 f4/thr), B tile 16x64 (2 f4/thr)
    int arow[2], ac4[2], brow[2], bc4[2];
    #pragma unroll
    for (int u = 0; u < 2; u++) {
        int l = tid * 2 + u;
        arow[u] = l >> 2;  ac4[u] = (l & 3) << 2;
        brow[u] = l >> 4;  bc4[u] = (l & 15) << 2;
    }

    float acc[2][4][4];
    #pragma unroll
    for (int mt = 0; mt < 2; mt++)
        #pragma unroll
        for (int nt = 0; nt < 4; nt++)
            #pragma unroll
            for (int i = 0; i < 4; i++) acc[mt][nt][i] = 0.0f;

    float4 avr[2], bvr[2];
    // prologue: stage kb=0
    #pragma unroll
    for (int u = 0; u < 2; u++) {
        avr[u] = *(const float4*)(A + (row0 + arow[u]) * D_ + ac4[u]);
        bvr[u] = *(const float4*)(W + (long long)brow[u] * H_ + col0 + bc4[u]);
    }
    #pragma unroll
    for (int u = 0; u < 2; u++) {
        float av[4] = {avr[u].x, avr[u].y, avr[u].z, avr[u].w};
        #pragma unroll
        for (int i = 0; i < 4; i++) {
            uint32_t hi = f2tf32(av[i]);
            float    hf = __uint_as_float(hi);
            AsHi[0][ac4[u] + i][arow[u]] = hi;
            AsLo[0][ac4[u] + i][arow[u]] = f2tf32(av[i] - hf);
        }
        float bv[4] = {bvr[u].x, bvr[u].y, bvr[u].z, bvr[u].w};
        #pragma unroll
        for (int i = 0; i < 4; i++)
            Bsm[0][brow[u]][bc4[u] + i] = f2tf32(bv[i]);
    }
    __syncthreads();

    constexpr int NKB = D_ / BK;   // 32
    for (int it = 0; it < NKB; it++) {
        const int cur = it & 1;
        if (it + 1 < NKB) {
            const int kb = (it + 1) * BK;
            #pragma unroll
            for (int u = 0; u < 2; u++) {
                avr[u] = *(const float4*)(A + (row0 + arow[u]) * D_ + kb + ac4[u]);
                bvr[u] = *(const float4*)(W + (long long)(kb + brow[u]) * H_ + col0 + bc4[u]);
            }
        }
        // two k8 steps per stage
        #pragma unroll
        for (int ks = 0; ks < 2; ks++) {
            const int k0 = ks * 8 + titg;
            uint32_t ahi[2][4], alo[2][4], bf[4][2];
            #pragma unroll
            for (int mt = 0; mt < 2; mt++) {
                const int m = m_base + mt * 16 + gid;
                ahi[mt][0] = AsHi[cur][k0][m];
                ahi[mt][1] = AsHi[cur][k0][m + 8];
                ahi[mt][2] = AsHi[cur][k0 + 4][m];
                ahi[mt][3] = AsHi[cur][k0 + 4][m + 8];
                alo[mt][0] = AsLo[cur][k0][m];
                alo[mt][1] = AsLo[cur][k0][m + 8];
                alo[mt][2] = AsLo[cur][k0 + 4][m];
                alo[mt][3] = AsLo[cur][k0 + 4][m + 8];
            }
            #pragma unroll
            for (int nt = 0; nt < 4; nt++) {
                const int n = n_base + nt * 8 + gid;
                bf[nt][0] = Bsm[cur][k0][n];
                bf[nt][1] = Bsm[cur][k0 + 4][n];
            }
            #pragma unroll
            for (int mt = 0; mt < 2; mt++)
                #pragma unroll
                for (int nt = 0; nt < 4; nt++) {
                    mma_tf32(acc[mt][nt], ahi[mt], bf[nt]);
                    mma_tf32(acc[mt][nt], alo[mt], bf[nt]);
                }
        }
        if (it + 1 < NKB) {
            const int nxt = 1 - cur;
            #pragma unroll
            for (int u = 0; u < 2; u++) {
                float av[4] = {avr[u].x, avr[u].y, avr[u].z, avr[u].w};
                #pragma unroll
                for (int i = 0; i < 4; i++) {
                    uint32_t hi = f2tf32(av[i]);
                    float    hf = __uint_as_float(hi);
                    AsHi[nxt][ac4[u] + i][arow[u]] = hi;
                    AsLo[nxt][ac4[u] + i][arow[u]] = f2tf32(av[i] - hf);
                }
                float bv[4] = {bvr[u].x, bvr[u].y, bvr[u].z, bvr[u].w};
                #pragma unroll
                for (int i = 0; i < 4; i++)
                    Bsm[nxt][brow[u]][bc4[u] + i] = f2tf32(bv[i]);
            }
            __syncthreads();
        }
    }

    // epilogue: D fragment c0=(gid,2t), c1=(gid,2t+1), c2=(gid+8,2t), c3=(gid+8,2t+1)
    if (isQ) {
        #pragma unroll
        for (int mt = 0; mt < 2; mt++) {
            const long long r_lo = row0 + m_base + mt * 16 + gid;
            #pragma unroll
            for (int nt = 0; nt < 4; nt++) {
                const int n = col0 + n_base + nt * 8 + 2 * titg;
                *(float2*)(g_qproj + r_lo * H_ + n) =
                    make_float2(acc[mt][nt][0], acc[mt][nt][1]);
                *(float2*)(g_qproj + (r_lo + 8) * H_ + n) =
                    make_float2(acc[mt][nt][2], acc[mt][nt][3]);
            }
        }
    } else {
        #pragma unroll
        for (int mt = 0; mt < 2; mt++) {
            const long long m = row0 + m_base + mt * 16 + gid;
            #pragma unroll
            for (int nt = 0; nt < 4; nt++) {
                const long long n = col0 + n_base + nt * 8 + 2 * titg;
                g_kprojT[n * MK + m]           = acc[mt][nt][0];
                g_kprojT[(n + 1) * MK + m]     = acc[mt][nt][1];
                g_kprojT[n * MK + m + 8]       = acc[mt][nt][2];
                g_kprojT[(n + 1) * MK + m + 8] = acc[mt][nt][3];
            }
        }
    }
}

// ----------------------------------------------------------------------------
// K2: masked tanh-scores, QT=4 (unchanged — near MUFU floor).
// grid = (32 q-tiles, 4 k-chunks, 8 b), 256 threads.
// ----------------------------------------------------------------------------
__global__ __launch_bounds__(256)
void scores_kernel(const float* __restrict__ wv, const int* __restrict__ vlens)
{
    constexpr int QT = 4;
    constexpr int HC = 16;
    constexpr int NCH = H_ / HC;
    __shared__ float s_tile[2][HC][256];
    __shared__ float s_q[QT][H_];
    __shared__ float s_wv[H_];

    const int b   = blockIdx.z;
    const int kp  = blockIdx.y;
    const int q0  = blockIdx.x * QT;
    const int tid = threadIdx.x;
    const int vlen = vlens[b];
    if (kp * 256 >= vlen) return;

    for (int i = tid; i < QT * H_; i += 256)
        s_q[i >> 8][i & 255] = g_qproj[(long long)(b * Q_ + q0 + (i >> 8)) * H_ + (i & 255)];
    for (int i = tid; i < H_; i += 256) s_wv[i] = wv[i];

    const float* kbase = g_kprojT + (long long)b * K_ + kp * 256;

    float4 rn[4];
    #pragma unroll
    for (int i = 0; i < 4; i++) {
        int idx = i * 256 + tid;
        int h = idx >> 6, c4 = (idx & 63) << 2;
        rn[i] = *(const float4*)(kbase + (long long)h * MK + c4);
    }
    #pragma unroll
    for (int i = 0; i < 4; i++) {
        int idx = i * 256 + tid;
        int h = idx >> 6, c4 = (idx & 63) << 2;
        *(float4*)&s_tile[0][h][c4] = rn[i];
    }
    __syncthreads();

    unsigned long long acc[QT] = {0ull, 0ull, 0ull, 0ull};

    for (int hc = 0; hc < NCH; hc++) {
        const int cur = hc & 1;
        if (hc + 1 < NCH) {
            #pragma unroll
            for (int i = 0; i < 4; i++) {
                int idx = i * 256 + tid;
                int h = idx >> 6, c4 = (idx & 63) << 2;
                rn[i] = *(const float4*)(kbase + (long long)((hc + 1) * HC + h) * MK + c4);
            }
        }
        const int hbase = hc * HC;
        #pragma unroll
        for (int hh = 0; hh < HC; hh += 2) {
            float kv0 = s_tile[cur][hh][tid];
            float kv1 = s_tile[cur][hh + 1][tid];
            unsigned long long kvp = pack2(kv0, kv1);
            float2 w2 = *(const float2*)&s_wv[hbase + hh];
            unsigned long long wvp = pack2(w2.x, w2.y);
            #pragma unroll
            for (int j = 0; j < QT; j++) {
                float2 q2 = *(const float2*)&s_q[j][hbase + hh];
                float2 sf = unpack2(add2(pack2(q2.x, q2.y), kvp));
                unsigned long long t = pack2(tanh_fast(sf.x), tanh_fast(sf.y));
                acc[j] = fma2(t, wvp, acc[j]);
            }
        }
        if (hc + 1 < NCH) {
            #pragma unroll
            for (int i = 0; i < 4; i++) {
                int idx = i * 256 + tid;
                int h = idx >> 6, c4 = (idx & 63) << 2;
                *(float4*)&s_tile[1 - cur][h][c4] = rn[i];
            }
            __syncthreads();
        }
    }

    const int k = kp * 256 + tid;
    if (k < vlen) {
        #pragma unroll
        for (int j = 0; j < QT; j++) {
            float2 r = unpack2(acc[j]);
            g_scores[(long long)(b * Q_ + q0 + j) * K_ + k] = r.x + r.y;
        }
    }
}

// ----------------------------------------------------------------------------
// K3: masked softmax + AV. QT=4 (round-8 measured-good version).
// grid = (32 q-tiles, 8 b), 256 threads.
// ----------------------------------------------------------------------------
__global__ __launch_bounds__(256)
void softmax_av(const int* __restrict__ vlens, const float* __restrict__ values,
                float* __restrict__ out)
{
    constexpr int QT = 4;
    __shared__ float s_sc[QT][K_];   // 16 KB
    __shared__ float s_red[8];

    const int b   = blockIdx.y;
    const int q0  = blockIdx.x * QT;
    const int tid = threadIdx.x;
    const int lane = tid & 31;
    const int wid  = tid >> 5;
    const int vlen = vlens[b];

    #pragma unroll
    for (int j = 0; j < QT; j++)
        for (int k = tid; k < vlen; k += 256)
            s_sc[j][k] = g_scores[(long long)(b * Q_ + q0 + j) * K_ + k];
    __syncthreads();

    float inv[QT];
    #pragma unroll 1
    for (int j = 0; j < QT; j++) {
        float m = -3.4e38f;
        for (int k = tid; k < vlen; k += 256) m = fmaxf(m, s_sc[j][k]);
        #pragma unroll
        for (int off = 16; off; off >>= 1)
            m = fmaxf(m, __shfl_xor_sync(0xffffffffu, m, off));
        if (lane == 0) s_red[wid] = m;
        __syncthreads();
        float mm = s_red[0];
        #pragma unroll
        for (int w = 1; w < 8; w++) mm = fmaxf(mm, s_red[w]);
        __syncthreads();

        float s = 0.f;
        for (int k = tid; k < vlen; k += 256) {
            float e = __expf(s_sc[j][k] - mm);
            s_sc[j][k] = e;
            s += e;
        }
        #pragma unroll
        for (int off = 16; off; off >>= 1)
            s += __shfl_xor_sync(0xffffffffu, s, off);
        if (lane == 0) s_red[wid] = s;
        __syncthreads();
        float ssum = 0.f;
        #pragma unroll
        for (int w = 0; w < 8; w++) ssum += s_red[w];
        inv[j] = 1.0f / ssum;
        __syncthreads();
    }

    const int v0 = tid * 2;
    const float* vb = values + (long long)b * K_ * V_ + v0;
    unsigned long long acc[QT] = {0ull, 0ull, 0ull, 0ull};
    int k = 0;
    #pragma unroll 1
    for (; k + 4 <= vlen; k += 4) {
        float2 vv0 = *(const float2*)(vb + (long long)(k + 0) * V_);
        float2 vv1 = *(const float2*)(vb + (long long)(k + 1) * V_);
        float2 vv2 = *(const float2*)(vb + (long long)(k + 2) * V_);
        float2 vv3 = *(const float2*)(vb + (long long)(k + 3) * V_);
        unsigned long long p0 = pack2(vv0.x, vv0.y);
        unsigned long long p1 = pack2(vv1.x, vv1.y);
        unsigned long long p2 = pack2(vv2.x, vv2.y);
        unsigned long long p3 = pack2(vv3.x, vv3.y);
        #pragma unroll
        for (int j = 0; j < QT; j++) {
            float e0 = s_sc[j][k], e1 = s_sc[j][k + 1];
            float e2 = s_sc[j][k + 2], e3 = s_sc[j][k + 3];
            acc[j] = fma2(pack2(e0, e0), p0, acc[j]);
            acc[j] = fma2(pack2(e1, e1), p1, acc[j]);
            acc[j] = fma2(pack2(e2, e2), p2, acc[j]);
            acc[j] = fma2(pack2(e3, e3), p3, acc[j]);
        }
    }
    for (; k < vlen; k++) {
        float2 vv = *(const float2*)(vb + (long long)k * V_);
        unsigned long long p = pack2(vv.x, vv.y);
        #pragma unroll
        for (int j = 0; j < QT; j++) {
            float e = s_sc[j][k];
            acc[j] = fma2(pack2(e, e), p, acc[j]);
        }
    }
    #pragma unroll
    for (int j = 0; j < QT; j++) {
        float2 r = unpack2(acc[j]);
        float2 o = make_float2(r.x * inv[j], r.y * inv[j]);
        *(float2*)(out + (long long)(b * Q_ + q0 + j) * V_ + v0) = o;
    }
}

// ----------------------------------------------------------------------------
extern "C" void kernel_launch(void* const* d_in, const int* in_sizes, int n_in,
                              void* d_out, int out_size)
{
    const float* queries = (const float*)d_in[0];  // [B,Q,D]
    const float* keys    = (const float*)d_in[1];  // [B,K,D]
    const float* values  = (const float*)d_in[2];  // [B,K,V]
    const int*   vlens   = (const int*)  d_in[3];  // [B]
    const float* Wq      = (const float*)d_in[4];  // [D,H]
    const float* Wk      = (const float*)d_in[5];  // [D,H]
    const float* wv      = (const float*)d_in[6];  // [H]
    float* out = (float*)d_out;                    // [B,Q,V]

    proj_gemm<<<dim3(H_ / 64, 16 + 128), 128>>>(queries, keys, Wq, Wk, vlens);
    scores_kernel<<<dim3(Q_ / 4, K_ / 256, B_), 256>>>(wv, vlens);
    softmax_av<<<dim3(Q_ / 4, B_), 256>>>(vlens, values, out);
}